// round 14
// baseline (speedup 1.0000x reference)
#include <cuda_runtime.h>
#include <cuda_bf16.h>
#include <mma.h>
using namespace nvcuda;

typedef unsigned long long u64t;
typedef unsigned int u32t;

__device__ __forceinline__ u64t ffma2(u64t a, u64t b, u64t c) {
    u64t d; asm("fma.rn.f32x2 %0, %1, %2, %3;" : "=l"(d) : "l"(a), "l"(b), "l"(c)); return d;
}
__device__ __forceinline__ u64t pack2(float lo, float hi) {
    u64t r; asm("mov.b64 %0, {%1, %2};" : "=l"(r) : "f"(lo), "f"(hi)); return r;
}
__device__ __forceinline__ float lo2(u64t v) {
    float f; asm("{ .reg .b32 t; mov.b64 {%0, t}, %1; }" : "=f"(f) : "l"(v)); return f;
}
__device__ __forceinline__ float hi2(u64t v) {
    float f; asm("{ .reg .b32 t; mov.b64 {t, %0}, %1; }" : "=f"(f) : "l"(v)); return f;
}
#define CVT_BF2(res, a, b) asm("cvt.rn.satfinite.bf16x2.f32 %0, %1, %2;" : "=r"(res) : "f"(b), "f"(a))

#define B_  64
#define NPIX 262144
#define PC 24
#define YC 72
#define H62 62
#define ATT 648
#define MVBLK 384

#define AS1 88
#define WS1 728
#define AST 56
#define WST 440

__device__ float g_y24[(size_t)NPIX*PC];
__device__ float g_y72[(size_t)NPIX*YC];
__device__ __nv_bfloat16 g_h1b[(size_t)B_*H62*H62*48];
__device__ float g_h2[(size_t)NPIX*48];
__device__ float g_x2[(size_t)NPIX*8];
__device__ float g_attpart[MVBLK*ATT];
__device__ float g_att[ATT];
__device__ float g_ssq_part[1024];
__device__ float g_scale;
__device__ uint4 g_W1w[4320];
__device__ uint4 g_Wtw[2592];
__device__ float g_Cpre[16*48];

// ---------------- weight prep ----------------
__global__ __launch_bounds__(256) void k_prepW(const float* __restrict__ W1,
                                               const float* __restrict__ Wt) {
    int idx = blockIdx.x * 256 + threadIdx.x;
    if (idx < 9 * 48 * 80) {
        int tap = idx / 3840, rem = idx % 3840, n = rem / 80, k = rem % 80;
        float v = (k < 72) ? W1[(size_t)(tap * 72 + k) * 48 + n] : 0.f;
        ((__nv_bfloat16*)g_W1w)[idx] = __float2bfloat16(v);
    } else if (idx < 9 * 48 * 80 + 9 * 48 * 48) {
        int j = idx - 9 * 48 * 80;
        int tap = j / 2304, rem = j % 2304, n = rem / 48, k = rem % 48;
        ((__nv_bfloat16*)g_Wtw)[j] = __float2bfloat16(Wt[(size_t)(tap * 48 + k) * 48 + n]);
    }
}

__global__ __launch_bounds__(768) void k_prepC(const float* __restrict__ b1,
                                               const float* __restrict__ Wt) {
    __shared__ float cv[9][48];
    int t = threadIdx.x;
    if (t < 432) {
        int tap = t / 48, n = t % 48;
        float s = 0.f;
#pragma unroll
        for (int k = 0; k < 48; k++) s += b1[k] * Wt[(size_t)(tap * 48 + k) * 48 + n];
        cv[tap][n] = s;
    }
    __syncthreads();
    if (t < 768) {
        int a = t / 192, rem = t % 192, b = rem / 48, n = rem % 48;
        float s = 0.f;
        for (int di = 0; di < a; di++)
            for (int dj = 0; dj < b; dj++) s += cv[di * 3 + dj][n];
        g_Cpre[t] = s;
    }
}

// ---------------- perceive ----------------
__global__ __launch_bounds__(256) void k_perceive(const float* __restrict__ x) {
    int pix = blockIdx.x * 256 + threadIdx.x;
    int w = pix & 63, h = (pix >> 6) & 63, b = pix >> 12;
    const float* xc = x + (size_t)pix * 8;
    float cen[8], s[8] = {0,0,0,0,0,0,0,0};
#pragma unroll
    for (int c = 0; c < 8; c++) cen[c] = xc[c];
#pragma unroll
    for (int dh = -1; dh <= 1; dh += 2)
#pragma unroll
        for (int dw = -1; dw <= 1; dw += 2) {
            int hh = h + dh, ww = w + dw;
            if ((unsigned)hh < 64u && (unsigned)ww < 64u) {
                const float* p = x + ((((size_t)(b << 6) + hh) << 6) + ww) * 8;
#pragma unroll
                for (int c = 0; c < 8; c++) s[c] += p[c];
            }
        }
    float* o = g_y24 + (size_t)pix * PC;
#pragma unroll
    for (int c = 0; c < 8; c++) {
        o[3*c] = cen[c]; o[3*c+1] = s[c] * 0.125f; o[3*c+2] = s[c] * 0.125f;
    }
}

// ---------------- attention matvec ----------------
__global__ __launch_bounds__(672) void k_att_mv(const float* __restrict__ Watt) {
    __shared__ float ys[256];
    __shared__ float4 part[3 * 162];
    int t = threadIdx.x;
    int i0 = blockIdx.x * 256;
    if (t < 256) ys[t] = g_y24[i0 + t];
    __syncthreads();
    float4 acc = {0.f, 0.f, 0.f, 0.f};
    int cq = t % 162, rq = t / 162;
    if (t < 648) {
        const float4* Wp = (const float4*)Watt + (size_t)(i0 + rq * 64) * 162 + cq;
#pragma unroll 8
        for (int r = 0; r < 64; r++) {
            float yv = ys[rq * 64 + r];
            float4 wv = Wp[(size_t)r * 162];
            acc.x += yv * wv.x; acc.y += yv * wv.y;
            acc.z += yv * wv.z; acc.w += yv * wv.w;
        }
        if (rq > 0) part[(rq - 1) * 162 + cq] = acc;
    }
    __syncthreads();
    if (t < 162) {
#pragma unroll
        for (int r = 0; r < 3; r++) {
            float4 v = part[r * 162 + cq];
            acc.x += v.x; acc.y += v.y; acc.z += v.z; acc.w += v.w;
        }
        ((float4*)g_attpart)[(size_t)blockIdx.x * 162 + cq] = acc;
    }
}

__global__ __launch_bounds__(256) void k_att_reduce(const float* __restrict__ b_att) {
    int t = blockIdx.x * 256 + threadIdx.x;
    if (t < ATT) {
        float s = b_att[t];
#pragma unroll 4
        for (int blk = 0; blk < MVBLK; blk++) s += g_attpart[blk * ATT + t];
        g_att[t] = s;
    }
}

// ---------------- dwconv2 + ssq ----------------
__global__ __launch_bounds__(256) void k_dwconv2() {
    int rg = blockIdx.x & 15, b = blockIdx.x >> 4;
    int r0 = rg * 4;
    __shared__ float rows[6][64 * 24];
    __shared__ float K[ATT];
    __shared__ float wred[8];
    int t = threadIdx.x;
    for (int j = t; j < ATT; j += 256) K[j] = g_att[j];
    for (int j = t; j < 6 * 1536; j += 256) {
        int rr = j / 1536, col = j % 1536;
        int hh = r0 - 1 + rr;
        rows[rr][col] = (hh >= 0 && hh < 64)
            ? g_y24[((size_t)((b << 6) + hh) << 6) * 24 + col] : 0.f;
    }
    __syncthreads();
    float ssq = 0.f;
    for (int it = t; it < 6144; it += 256) {
        int c = it % 24, w = (it / 24) & 63, lr = it / 1536;
        float a0 = 0.f, a1 = 0.f, a2 = 0.f;
#pragma unroll
        for (int rr = 0; rr < 3; rr++) {
            const float* rp = rows[lr + rr];
#pragma unroll
            for (int dw = 0; dw < 3; dw++) {
                int ww = w + dw - 1;
                float v = ((unsigned)ww < 64u) ? rp[ww * 24 + c] : 0.f;
                int kb = (rr * 3 + dw) * 72 + c * 3;
                a0 += v * K[kb]; a1 += v * K[kb + 1]; a2 += v * K[kb + 2];
            }
        }
        float* o = g_y72 + ((size_t)(((b << 6) + r0 + lr) << 6) + w) * YC + c * 3;
        o[0] = a0; o[1] = a1; o[2] = a2;
        ssq += a0 * a0 + a1 * a1 + a2 * a2;
    }
#pragma unroll
    for (int s = 16; s; s >>= 1) ssq += __shfl_xor_sync(~0u, ssq, s);
    if ((t & 31) == 0) wred[t >> 5] = ssq;
    __syncthreads();
    if (t == 0) {
        float s = 0.f;
#pragma unroll
        for (int i = 0; i < 8; i++) s += wred[i];
        g_ssq_part[blockIdx.x] = s;
    }
}

__global__ __launch_bounds__(1024) void k_ssq_reduce() {
    __shared__ float red[1024];
    int t = threadIdx.x;
    red[t] = g_ssq_part[t];
    __syncthreads();
    for (int k = 512; k > 0; k >>= 1) { if (t < k) red[t] += red[t + k]; __syncthreads(); }
    if (t == 0) g_scale = rsqrtf(fmaxf(red[0], 1e-12f));
}

// ---------------- conv1 wmma, software-pipelined ----------------
#define C1_SMEM (10*64*AS1*2 + 48*WS1*2)
__global__ __launch_bounds__(512, 1) void k_conv1w() {
    extern __shared__ __align__(16) __nv_bfloat16 smc1[];
    __nv_bfloat16* sA = smc1;
    __nv_bfloat16* sW = smc1 + 10 * 64 * AS1;
    int b = blockIdx.x >> 3, rg = blockIdx.x & 7;
    int r0 = rg * 8;
    int t = threadIdx.x, w = t >> 5;
    int wr = w >> 1, wc = (w & 1) * 32;
    float scale = g_scale;
    for (int j = t; j < 4320; j += 512) {
        int tap = j / 480, rem = j % 480, n = rem / 10, kq = rem % 10;
        *(uint4*)(sW + n * WS1 + tap * 80 + kq * 8) = g_W1w[j];
    }
    for (int j = t; j < 12800; j += 512) {
        int kq = j % 20, pc = j / 20;
        int r = pc >> 6, gr = r0 + r;
        uint2 st = make_uint2(0u, 0u);
        if (kq < 18 && gr < 64) {
            float4 v = *(const float4*)(g_y72 +
                ((size_t)((b << 6) + gr) * 64 + (pc & 63)) * YC + kq * 4);
            CVT_BF2(st.x, v.x * scale, v.y * scale);
            CVT_BF2(st.y, v.z * scale, v.w * scale);
        }
        *(uint2*)(sA + pc * AS1 + kq * 4) = st;
    }
    __syncthreads();

    wmma::fragment<wmma::accumulator, 16, 16, 16, float> acc[2][3];
#pragma unroll
    for (int m = 0; m < 2; m++)
#pragma unroll
        for (int nt = 0; nt < 3; nt++) wmma::fill_fragment(acc[m][nt], 0.f);

    wmma::fragment<wmma::matrix_a, 16, 16, 16, __nv_bfloat16, wmma::row_major> fa0[2], fa1[2];
    wmma::fragment<wmma::matrix_b, 16, 16, 16, __nv_bfloat16, wmma::col_major> fb0[3], fb1[3];

#define C1_LOAD(S, FA, FB) do { \
    int _tap = (S) / 5, _ks = (S) % 5; \
    int _di = _tap / 3, _dj = _tap % 3; \
    const __nv_bfloat16* _ar = sA + ((wr + _di) * 64 + wc + _dj) * AS1 + _ks * 16; \
    const __nv_bfloat16* _wr2 = sW + _tap * 80 + _ks * 16; \
    wmma::load_matrix_sync(FA[0], _ar, AS1); \
    wmma::load_matrix_sync(FA[1], _ar + 16 * AS1, AS1); \
    wmma::load_matrix_sync(FB[0], _wr2, WS1); \
    wmma::load_matrix_sync(FB[1], _wr2 + 16 * WS1, WS1); \
    wmma::load_matrix_sync(FB[2], _wr2 + 32 * WS1, WS1); \
} while (0)
#define C_MMA(FA, FB) do { \
    _Pragma("unroll") \
    for (int _nt = 0; _nt < 3; _nt++) { \
        wmma::mma_sync(acc[0][_nt], FA[0], FB[_nt], acc[0][_nt]); \
        wmma::mma_sync(acc[1][_nt], FA[1], FB[_nt], acc[1][_nt]); \
    } \
} while (0)

    C1_LOAD(0, fa0, fb0);
#pragma unroll 1
    for (int s = 0; s < 44; s += 2) {
        C1_LOAD(s + 1, fa1, fb1);
        C_MMA(fa0, fb0);
        C1_LOAD(s + 2, fa0, fb0);
        C_MMA(fa1, fb1);
    }
    C_MMA(fa0, fb0);   // step 44

    __syncthreads();
    float* sOut = (float*)sA;
#pragma unroll
    for (int m = 0; m < 2; m++)
#pragma unroll
        for (int nt = 0; nt < 3; nt++)
            wmma::store_matrix_sync(sOut + (wr * 64 + wc + m * 16) * 48 + nt * 16, acc[m][nt],
                                    48, wmma::mem_row_major);
    __syncthreads();
    {
        int p = t;
        int r = r0 + (p >> 6), c = p & 63;
        if (r < H62 && c < H62) {
            const float* src = sOut + p * 48;
            u32t pk[24];
#pragma unroll
            for (int i = 0; i < 24; i++) CVT_BF2(pk[i], src[2*i], src[2*i+1]);
            uint4* o = (uint4*)(g_h1b + ((size_t)(b * H62 + r) * H62 + c) * 48);
#pragma unroll
            for (int q = 0; q < 6; q++)
                o[q] = make_uint4(pk[4*q], pk[4*q+1], pk[4*q+2], pk[4*q+3]);
        }
    }
}

// ---------------- convt wmma, software-pipelined ----------------
#define CT_SMEM (12*68*AST*2 + 48*WST*2 + 768*4)
__global__ __launch_bounds__(512, 1) void k_convtw(const float* __restrict__ bt) {
    extern __shared__ __align__(16) __nv_bfloat16 smct[];
    __nv_bfloat16* sA = smct;
    __nv_bfloat16* sW = smct + 12 * 68 * AST;
    float* sC = (float*)((char*)smct + 12*68*AST*2 + 48*WST*2);
    int b = blockIdx.x >> 3, rg = blockIdx.x & 7;
    int r0 = rg * 8;
    int t = threadIdx.x, w = t >> 5;
    int wr = w >> 1, wc = (w & 1) * 32;
    for (int j = t; j < 768; j += 512) sC[j] = g_Cpre[j];
    for (int j = t; j < 2592; j += 512) {
        int tap = j / 288, rem = j % 288, n = rem / 6, kq = rem % 6;
        *(uint4*)(sW + n * WST + tap * 48 + kq * 8) = g_Wtw[j];
    }
    for (int j = t; j < 12 * 68 * 6; j += 512) {
        int q = j % 6, pc = j / 6;
        int r = pc / 68, c = pc % 68;
        int gr = r0 + r - 2, gc = c - 2;
        uint4 v = make_uint4(0u, 0u, 0u, 0u);
        if ((unsigned)gr < (unsigned)H62 && (unsigned)gc < (unsigned)H62)
            v = *(const uint4*)(g_h1b + ((size_t)(b * H62 + gr) * H62 + gc) * 48 + q * 8);
        *(uint4*)(sA + pc * AST + q * 8) = v;
    }
    __syncthreads();

    wmma::fragment<wmma::accumulator, 16, 16, 16, float> acc[2][3];
#pragma unroll
    for (int m = 0; m < 2; m++)
#pragma unroll
        for (int nt = 0; nt < 3; nt++) wmma::fill_fragment(acc[m][nt], 0.f);

    wmma::fragment<wmma::matrix_a, 16, 16, 16, __nv_bfloat16, wmma::row_major> fa0[2], fa1[2];
    wmma::fragment<wmma::matrix_b, 16, 16, 16, __nv_bfloat16, wmma::col_major> fb0[3], fb1[3];

#define CT_LOAD(S, FA, FB) do { \
    int _tap = (S) / 3, _ks = (S) % 3; \
    int _di = _tap / 3, _dj = _tap % 3; \
    const __nv_bfloat16* _ar = sA + ((wr + _di) * 68 + wc + _dj) * AST + _ks * 16; \
    const __nv_bfloat16* _wr2 = sW + _tap * 48 + _ks * 16; \
    wmma::load_matrix_sync(FA[0], _ar, AST); \
    wmma::load_matrix_sync(FA[1], _ar + 16 * AST, AST); \
    wmma::load_matrix_sync(FB[0], _wr2, WST); \
    wmma::load_matrix_sync(FB[1], _wr2 + 16 * WST, WST); \
    wmma::load_matrix_sync(FB[2], _wr2 + 32 * WST, WST); \
} while (0)

    CT_LOAD(0, fa0, fb0);
#pragma unroll 1
    for (int s = 0; s < 26; s += 2) {
        CT_LOAD(s + 1, fa1, fb1);
        C_MMA(fa0, fb0);
        CT_LOAD(s + 2, fa0, fb0);
        C_MMA(fa1, fb1);
    }
    C_MMA(fa0, fb0);   // step 26

    __syncthreads();
    float* sOut = (float*)sA;
#pragma unroll
    for (int m = 0; m < 2; m++)
#pragma unroll
        for (int nt = 0; nt < 3; nt++)
            wmma::store_matrix_sync(sOut + (wr * 64 + wc + m * 16) * 48 + nt * 16, acc[m][nt],
                                    48, wmma::mem_row_major);
    __syncthreads();
    {
        int p = t;
        int i = r0 + (p >> 6), c = p & 63;
        int a0 = 2 - i; if (a0 < 0) a0 = 0;
        int a1 = 64 - i; if (a1 > 3) a1 = 3;
        int b0 = 2 - c; if (b0 < 0) b0 = 0;
        int b1c = 64 - c; if (b1c > 3) b1c = 3;
        const float* P11 = sC + (a1 * 4 + b1c) * 48;
        const float* P01 = sC + (a0 * 4 + b1c) * 48;
        const float* P10 = sC + (a1 * 4 + b0) * 48;
        const float* P00 = sC + (a0 * 4 + b0) * 48;
        const float* src = sOut + p * 48;
        float4* ov = (float4*)(g_h2 + ((size_t)((b << 6) + i) * 64 + c) * 48);
#pragma unroll
        for (int q = 0; q < 12; q++) {
            float4 r;
#pragma unroll
            for (int e = 0; e < 4; e++) {
                int idx = 4 * q + e;
                ((float*)&r)[e] = src[idx] + bt[idx] + P11[idx] - P01[idx] - P10[idx] + P00[idx];
            }
            ov[q] = r;
        }
    }
}

// ---------------- head ----------------
__global__ __launch_bounds__(256) void k_head(const float* __restrict__ x,
        const float* __restrict__ noise, const float* __restrict__ W2,
        const float* __restrict__ b2, const float* __restrict__ W3,
        const float* __restrict__ b3) {
    __shared__ float sW2[48 * 128];
    __shared__ float sW3[128 * 8];
    __shared__ float sb2[128];
    __shared__ float sb3[8];
    int t = threadIdx.x;
    for (int j = t; j < 48 * 128; j += 256) sW2[j] = W2[j];
    for (int j = t; j < 128 * 8; j += 256) sW3[j] = W3[j];
    if (t < 128) sb2[t] = b2[t];
    if (t < 8) sb3[t] = b3[t];
    __syncthreads();
    int pix = blockIdx.x * 256 + t;
    float h[48];
    const float4* hp = (const float4*)(g_h2 + (size_t)pix * 48);
#pragma unroll
    for (int i = 0; i < 12; i++) {
        float4 v = hp[i];
        h[4*i] = v.x; h[4*i+1] = v.y; h[4*i+2] = v.z; h[4*i+3] = v.w;
    }
    u64t dx[4];
#pragma unroll
    for (int q = 0; q < 4; q++) dx[q] = *(const u64t*)&sb3[2 * q];
#pragma unroll 1
    for (int chk = 0; chk < 4; chk++) {
        int O = chk * 32;
        u64t z[16];
#pragma unroll
        for (int i = 0; i < 16; i++) z[i] = *(const u64t*)&sb2[O + 2 * i];
#pragma unroll 1
        for (int c = 0; c < 48; c++) {
            u64t hd = pack2(h[c], h[c]);
            const ulonglong2* wp = (const ulonglong2*)&sW2[c * 128 + O];
#pragma unroll
            for (int j = 0; j < 8; j++) {
                ulonglong2 ww = wp[j];
                z[2*j]   = ffma2(hd, ww.x, z[2*j]);
                z[2*j+1] = ffma2(hd, ww.y, z[2*j+1]);
            }
        }
#pragma unroll
        for (int i = 0; i < 16; i++) {
            float za = fmaxf(lo2(z[i]), 0.f), zb = fmaxf(hi2(z[i]), 0.f);
            int o = O + 2 * i;
            u64t da = pack2(za, za), db = pack2(zb, zb);
            const u64t* w3a = (const u64t*)&sW3[o * 8];
            const u64t* w3b = (const u64t*)&sW3[o * 8 + 8];
#pragma unroll
            for (int q = 0; q < 4; q++) {
                dx[q] = ffma2(da, w3a[q], dx[q]);
                dx[q] = ffma2(db, w3b[q], dx[q]);
            }
        }
    }
    float mask = (noise[pix] <= 0.5f) ? 1.f : 0.f;
    const float* xp = x + (size_t)pix * 8;
    float* o2 = g_x2 + (size_t)pix * 8;
#pragma unroll
    for (int q = 0; q < 4; q++) {
        o2[2*q]   = xp[2*q]   + lo2(dx[q]) * mask;
        o2[2*q+1] = xp[2*q+1] + hi2(dx[q]) * mask;
    }
}

// ---------------- life mask ----------------
__global__ __launch_bounds__(256) void k_life(const float* __restrict__ x,
                                              float* __restrict__ out) {
    int pix = blockIdx.x * 256 + threadIdx.x;
    int w = pix & 63, h = (pix >> 6) & 63, b = pix >> 12;
    float pre = -1e30f, post = -1e30f;
#pragma unroll
    for (int dh = -1; dh <= 1; dh++)
#pragma unroll
        for (int dw = -1; dw <= 1; dw++) {
            int hh = h + dh, ww = w + dw;
            if ((unsigned)hh < 64u && (unsigned)ww < 64u) {
                size_t idx = ((((size_t)(b << 6) + hh) << 6) + ww) * 8 + 3;
                pre = fmaxf(pre, x[idx]);
                post = fmaxf(post, g_x2[idx]);
            }
        }
    float life = (pre > 0.1f && post > 0.1f) ? 1.f : 0.f;
    const float* s = g_x2 + (size_t)pix * 8;
    float* o = out + (size_t)pix * 8;
#pragma unroll
    for (int k = 0; k < 8; k++) o[k] = s[k] * life;
}

// ---------------- launch ----------------
extern "C" void kernel_launch(void* const* d_in, const int* in_sizes, int n_in,
                              void* d_out, int out_size) {
    const float* x     = (const float*)d_in[0];
    const float* noise = (const float*)d_in[1];
    const float* Watt  = (const float*)d_in[2];
    const float* batt  = (const float*)d_in[3];
    const float* W1    = (const float*)d_in[4];
    const float* b1    = (const float*)d_in[5];
    const float* Wt    = (const float*)d_in[6];
    const float* bt    = (const float*)d_in[7];
    const float* W2    = (const float*)d_in[8];
    const float* b2    = (const float*)d_in[9];
    const float* W3    = (const float*)d_in[10];
    const float* b3    = (const float*)d_in[11];
    float* out = (float*)d_out;

    cudaFuncSetAttribute(k_conv1w, cudaFuncAttributeMaxDynamicSharedMemorySize, C1_SMEM);
    cudaFuncSetAttribute(k_convtw, cudaFuncAttributeMaxDynamicSharedMemorySize, CT_SMEM);

    k_perceive<<<1024, 256>>>(x);
    k_att_mv<<<MVBLK, 672>>>(Watt);
    k_att_reduce<<<3, 256>>>(batt);
    k_dwconv2<<<1024, 256>>>();
    k_ssq_reduce<<<1, 1024>>>();
    k_prepW<<<216, 256>>>(W1, Wt);
    k_prepC<<<1, 768>>>(b1, Wt);
    k_conv1w<<<512, 512, C1_SMEM>>>();
    k_convtw<<<512, 512, CT_SMEM>>>(bt);
    k_head<<<1024, 256>>>(x, noise, W2, b2, W3, b3);
    k_life<<<1024, 256>>>(x, out);
}

// round 15
// speedup vs baseline: 1.4619x; 1.4619x over previous
#include <cuda_runtime.h>
#include <cuda_bf16.h>
#include <mma.h>
using namespace nvcuda;

typedef unsigned long long u64t;
typedef unsigned int u32t;

__device__ __forceinline__ u64t ffma2(u64t a, u64t b, u64t c) {
    u64t d; asm("fma.rn.f32x2 %0, %1, %2, %3;" : "=l"(d) : "l"(a), "l"(b), "l"(c)); return d;
}
__device__ __forceinline__ u64t pack2(float lo, float hi) {
    u64t r; asm("mov.b64 %0, {%1, %2};" : "=l"(r) : "f"(lo), "f"(hi)); return r;
}
__device__ __forceinline__ float lo2(u64t v) {
    float f; asm("{ .reg .b32 t; mov.b64 {%0, t}, %1; }" : "=f"(f) : "l"(v)); return f;
}
__device__ __forceinline__ float hi2(u64t v) {
    float f; asm("{ .reg .b32 t; mov.b64 {t, %0}, %1; }" : "=f"(f) : "l"(v)); return f;
}
#define CVT_BF2(res, a, b) asm("cvt.rn.satfinite.bf16x2.f32 %0, %1, %2;" : "=r"(res) : "f"(b), "f"(a))

#define B_  64
#define NPIX 262144
#define PC 24
#define YC 72
#define H62 62
#define ATT 648
#define MVBLK 384

#define AS1 88      // conv1 A k-stride (11*16B, conflict-free LDSM)
#define WS1 728     // conv1 W k-stride
#define AST 56      // convt A k-stride
#define WST 440     // convt W k-stride

__device__ float g_y24[(size_t)NPIX*PC];
__device__ float g_y72[(size_t)NPIX*YC];
__device__ __nv_bfloat16 g_h1b[(size_t)B_*H62*H62*48];
__device__ float g_h2[(size_t)NPIX*48];
__device__ float g_x2[(size_t)NPIX*8];
__device__ float g_attpart[MVBLK*ATT];
__device__ float g_att[ATT];
__device__ float g_ssq_part[1024];
__device__ float g_scale;
__device__ uint4 g_W1w[4320];   // bf16 [9][48][80]
__device__ uint4 g_Wtw[2592];   // bf16 [9][48][48]
__device__ float g_Cpre[16*48];

// ---------------- weight prep ----------------
__global__ __launch_bounds__(256) void k_prepW(const float* __restrict__ W1,
                                               const float* __restrict__ Wt) {
    int idx = blockIdx.x * 256 + threadIdx.x;
    if (idx < 9 * 48 * 80) {
        int tap = idx / 3840, rem = idx % 3840, n = rem / 80, k = rem % 80;
        float v = (k < 72) ? W1[(size_t)(tap * 72 + k) * 48 + n] : 0.f;
        ((__nv_bfloat16*)g_W1w)[idx] = __float2bfloat16(v);
    } else if (idx < 9 * 48 * 80 + 9 * 48 * 48) {
        int j = idx - 9 * 48 * 80;
        int tap = j / 2304, rem = j % 2304, n = rem / 48, k = rem % 48;
        ((__nv_bfloat16*)g_Wtw)[j] = __float2bfloat16(Wt[(size_t)(tap * 48 + k) * 48 + n]);
    }
}

__global__ __launch_bounds__(768) void k_prepC(const float* __restrict__ b1,
                                               const float* __restrict__ Wt) {
    __shared__ float cv[9][48];
    int t = threadIdx.x;
    if (t < 432) {
        int tap = t / 48, n = t % 48;
        float s = 0.f;
#pragma unroll
        for (int k = 0; k < 48; k++) s += b1[k] * Wt[(size_t)(tap * 48 + k) * 48 + n];
        cv[tap][n] = s;
    }
    __syncthreads();
    if (t < 768) {
        int a = t / 192, rem = t % 192, b = rem / 48, n = rem % 48;
        float s = 0.f;
        for (int di = 0; di < a; di++)
            for (int dj = 0; dj < b; dj++) s += cv[di * 3 + dj][n];
        g_Cpre[t] = s;
    }
}

// ---------------- perceive ----------------
__global__ __launch_bounds__(256) void k_perceive(const float* __restrict__ x) {
    int pix = blockIdx.x * 256 + threadIdx.x;
    int w = pix & 63, h = (pix >> 6) & 63, b = pix >> 12;
    const float* xc = x + (size_t)pix * 8;
    float cen[8], s[8] = {0,0,0,0,0,0,0,0};
#pragma unroll
    for (int c = 0; c < 8; c++) cen[c] = xc[c];
#pragma unroll
    for (int dh = -1; dh <= 1; dh += 2)
#pragma unroll
        for (int dw = -1; dw <= 1; dw += 2) {
            int hh = h + dh, ww = w + dw;
            if ((unsigned)hh < 64u && (unsigned)ww < 64u) {
                const float* p = x + ((((size_t)(b << 6) + hh) << 6) + ww) * 8;
#pragma unroll
                for (int c = 0; c < 8; c++) s[c] += p[c];
            }
        }
    float* o = g_y24 + (size_t)pix * PC;
#pragma unroll
    for (int c = 0; c < 8; c++) {
        o[3*c] = cen[c]; o[3*c+1] = s[c] * 0.125f; o[3*c+2] = s[c] * 0.125f;
    }
}

// ---------------- attention matvec ----------------
__global__ __launch_bounds__(672) void k_att_mv(const float* __restrict__ Watt) {
    __shared__ float ys[256];
    __shared__ float4 part[3 * 162];
    int t = threadIdx.x;
    int i0 = blockIdx.x * 256;
    if (t < 256) ys[t] = g_y24[i0 + t];
    __syncthreads();
    float4 acc = {0.f, 0.f, 0.f, 0.f};
    int cq = t % 162, rq = t / 162;
    if (t < 648) {
        const float4* Wp = (const float4*)Watt + (size_t)(i0 + rq * 64) * 162 + cq;
#pragma unroll 8
        for (int r = 0; r < 64; r++) {
            float yv = ys[rq * 64 + r];
            float4 wv = Wp[(size_t)r * 162];
            acc.x += yv * wv.x; acc.y += yv * wv.y;
            acc.z += yv * wv.z; acc.w += yv * wv.w;
        }
        if (rq > 0) part[(rq - 1) * 162 + cq] = acc;
    }
    __syncthreads();
    if (t < 162) {
#pragma unroll
        for (int r = 0; r < 3; r++) {
            float4 v = part[r * 162 + cq];
            acc.x += v.x; acc.y += v.y; acc.z += v.z; acc.w += v.w;
        }
        ((float4*)g_attpart)[(size_t)blockIdx.x * 162 + cq] = acc;
    }
}

__global__ __launch_bounds__(256) void k_att_reduce(const float* __restrict__ b_att) {
    int t = blockIdx.x * 256 + threadIdx.x;
    if (t < ATT) {
        float s = b_att[t];
#pragma unroll 4
        for (int blk = 0; blk < MVBLK; blk++) s += g_attpart[blk * ATT + t];
        g_att[t] = s;
    }
}

// ---------------- dwconv2 + ssq ----------------
__global__ __launch_bounds__(256) void k_dwconv2() {
    int rg = blockIdx.x & 15, b = blockIdx.x >> 4;
    int r0 = rg * 4;
    __shared__ float rows[6][64 * 24];
    __shared__ float K[ATT];
    __shared__ float wred[8];
    int t = threadIdx.x;
    for (int j = t; j < ATT; j += 256) K[j] = g_att[j];
    for (int j = t; j < 6 * 1536; j += 256) {
        int rr = j / 1536, col = j % 1536;
        int hh = r0 - 1 + rr;
        rows[rr][col] = (hh >= 0 && hh < 64)
            ? g_y24[((size_t)((b << 6) + hh) << 6) * 24 + col] : 0.f;
    }
    __syncthreads();
    float ssq = 0.f;
    for (int it = t; it < 6144; it += 256) {
        int c = it % 24, w = (it / 24) & 63, lr = it / 1536;
        float a0 = 0.f, a1 = 0.f, a2 = 0.f;
#pragma unroll
        for (int rr = 0; rr < 3; rr++) {
            const float* rp = rows[lr + rr];
#pragma unroll
            for (int dw = 0; dw < 3; dw++) {
                int ww = w + dw - 1;
                float v = ((unsigned)ww < 64u) ? rp[ww * 24 + c] : 0.f;
                int kb = (rr * 3 + dw) * 72 + c * 3;
                a0 += v * K[kb]; a1 += v * K[kb + 1]; a2 += v * K[kb + 2];
            }
        }
        float* o = g_y72 + ((size_t)(((b << 6) + r0 + lr) << 6) + w) * YC + c * 3;
        o[0] = a0; o[1] = a1; o[2] = a2;
        ssq += a0 * a0 + a1 * a1 + a2 * a2;
    }
#pragma unroll
    for (int s = 16; s; s >>= 1) ssq += __shfl_xor_sync(~0u, ssq, s);
    if ((t & 31) == 0) wred[t >> 5] = ssq;
    __syncthreads();
    if (t == 0) {
        float s = 0.f;
#pragma unroll
        for (int i = 0; i < 8; i++) s += wred[i];
        g_ssq_part[blockIdx.x] = s;
    }
}

__global__ __launch_bounds__(1024) void k_ssq_reduce() {
    __shared__ float red[1024];
    int t = threadIdx.x;
    red[t] = g_ssq_part[t];
    __syncthreads();
    for (int k = 512; k > 0; k >>= 1) { if (t < k) red[t] += red[t + k]; __syncthreads(); }
    if (t == 0) g_scale = rsqrtf(fmaxf(red[0], 1e-12f));
}

// ---------------- conv1 wmma: 8 rows x 64 cols, 16 warps, warp M=32 x N=48 ----------------
#define C1_SMEM (10*64*AS1*2 + 48*WS1*2)
__global__ __launch_bounds__(512, 1) void k_conv1w() {
    extern __shared__ __align__(16) __nv_bfloat16 smc1[];
    __nv_bfloat16* sA = smc1;
    __nv_bfloat16* sW = smc1 + 10 * 64 * AS1;
    int b = blockIdx.x >> 3, rg = blockIdx.x & 7;
    int r0 = rg * 8;
    int t = threadIdx.x, w = t >> 5;
    int wr = w >> 1, wc = (w & 1) * 32;
    float scale = g_scale;
    for (int j = t; j < 4320; j += 512) {
        int tap = j / 480, rem = j % 480, n = rem / 10, kq = rem % 10;
        *(uint4*)(sW + n * WS1 + tap * 80 + kq * 8) = g_W1w[j];
    }
    for (int j = t; j < 12800; j += 512) {
        int kq = j % 20, pc = j / 20;
        int r = pc >> 6, gr = r0 + r;
        uint2 st = make_uint2(0u, 0u);
        if (kq < 18 && gr < 64) {
            float4 v = *(const float4*)(g_y72 +
                ((size_t)((b << 6) + gr) * 64 + (pc & 63)) * YC + kq * 4);
            CVT_BF2(st.x, v.x * scale, v.y * scale);
            CVT_BF2(st.y, v.z * scale, v.w * scale);
        }
        *(uint2*)(sA + pc * AS1 + kq * 4) = st;
    }
    __syncthreads();

    wmma::fragment<wmma::accumulator, 16, 16, 16, float> acc[2][3];
#pragma unroll
    for (int m = 0; m < 2; m++)
#pragma unroll
        for (int nt = 0; nt < 3; nt++) wmma::fill_fragment(acc[m][nt], 0.f);

#pragma unroll 1
    for (int tap = 0; tap < 9; tap++) {
        int di = tap / 3, dj = tap % 3;
        const __nv_bfloat16* arow = sA + ((wr + di) * 64 + wc + dj) * AS1;
        const __nv_bfloat16* wrow = sW + tap * 80;
#pragma unroll 1
        for (int ks = 0; ks < 5; ks++) {
            wmma::fragment<wmma::matrix_a, 16, 16, 16, __nv_bfloat16, wmma::row_major> fa[2];
            wmma::fragment<wmma::matrix_b, 16, 16, 16, __nv_bfloat16, wmma::col_major> fb[3];
#pragma unroll
            for (int m = 0; m < 2; m++)
                wmma::load_matrix_sync(fa[m], arow + m * 16 * AS1 + ks * 16, AS1);
#pragma unroll
            for (int nt = 0; nt < 3; nt++)
                wmma::load_matrix_sync(fb[nt], wrow + nt * 16 * WS1 + ks * 16, WS1);
#pragma unroll
            for (int nt = 0; nt < 3; nt++)
#pragma unroll
                for (int m = 0; m < 2; m++)
                    wmma::mma_sync(acc[m][nt], fa[m], fb[nt], acc[m][nt]);
        }
    }
    __syncthreads();
    float* sOut = (float*)sA;
#pragma unroll
    for (int m = 0; m < 2; m++)
#pragma unroll
        for (int nt = 0; nt < 3; nt++)
            wmma::store_matrix_sync(sOut + (wr * 64 + wc + m * 16) * 48 + nt * 16, acc[m][nt],
                                    48, wmma::mem_row_major);
    __syncthreads();
    {
        int p = t;
        int r = r0 + (p >> 6), c = p & 63;
        if (r < H62 && c < H62) {
            const float* src = sOut + p * 48;
            u32t pk[24];
#pragma unroll
            for (int i = 0; i < 24; i++) CVT_BF2(pk[i], src[2*i], src[2*i+1]);
            uint4* o = (uint4*)(g_h1b + ((size_t)(b * H62 + r) * H62 + c) * 48);
#pragma unroll
            for (int q = 0; q < 6; q++)
                o[q] = make_uint4(pk[4*q], pk[4*q+1], pk[4*q+2], pk[4*q+3]);
        }
    }
}

// ---------------- convt wmma: 8 rows x 64, 16 warps, warp M=32 x N=48, pad 2 ----------------
#define CT_SMEM (12*68*AST*2 + 48*WST*2 + 768*4)
__global__ __launch_bounds__(512, 1) void k_convtw(const float* __restrict__ bt) {
    extern __shared__ __align__(16) __nv_bfloat16 smct[];
    __nv_bfloat16* sA = smct;
    __nv_bfloat16* sW = smct + 12 * 68 * AST;
    float* sC = (float*)((char*)smct + 12*68*AST*2 + 48*WST*2);
    int b = blockIdx.x >> 3, rg = blockIdx.x & 7;
    int r0 = rg * 8;
    int t = threadIdx.x, w = t >> 5;
    int wr = w >> 1, wc = (w & 1) * 32;
    for (int j = t; j < 768; j += 512) sC[j] = g_Cpre[j];
    for (int j = t; j < 2592; j += 512) {
        int tap = j / 288, rem = j % 288, n = rem / 6, kq = rem % 6;
        *(uint4*)(sW + n * WST + tap * 48 + kq * 8) = g_Wtw[j];
    }
    for (int j = t; j < 12 * 68 * 6; j += 512) {
        int q = j % 6, pc = j / 6;
        int r = pc / 68, c = pc % 68;
        int gr = r0 + r - 2, gc = c - 2;
        uint4 v = make_uint4(0u, 0u, 0u, 0u);
        if ((unsigned)gr < (unsigned)H62 && (unsigned)gc < (unsigned)H62)
            v = *(const uint4*)(g_h1b + ((size_t)(b * H62 + gr) * H62 + gc) * 48 + q * 8);
        *(uint4*)(sA + pc * AST + q * 8) = v;
    }
    __syncthreads();

    wmma::fragment<wmma::accumulator, 16, 16, 16, float> acc[2][3];
#pragma unroll
    for (int m = 0; m < 2; m++)
#pragma unroll
        for (int nt = 0; nt < 3; nt++) wmma::fill_fragment(acc[m][nt], 0.f);

#pragma unroll 1
    for (int tap = 0; tap < 9; tap++) {
        int di = tap / 3, dj = tap % 3;
        const __nv_bfloat16* arow = sA + ((wr + di) * 68 + wc + dj) * AST;
        const __nv_bfloat16* wrow = sW + tap * 48;
#pragma unroll 1
        for (int ks = 0; ks < 3; ks++) {
            wmma::fragment<wmma::matrix_a, 16, 16, 16, __nv_bfloat16, wmma::row_major> fa[2];
            wmma::fragment<wmma::matrix_b, 16, 16, 16, __nv_bfloat16, wmma::col_major> fb[3];
#pragma unroll
            for (int m = 0; m < 2; m++)
                wmma::load_matrix_sync(fa[m], arow + m * 16 * AST + ks * 16, AST);
#pragma unroll
            for (int nt = 0; nt < 3; nt++)
                wmma::load_matrix_sync(fb[nt], wrow + nt * 16 * WST + ks * 16, WST);
#pragma unroll
            for (int nt = 0; nt < 3; nt++)
#pragma unroll
                for (int m = 0; m < 2; m++)
                    wmma::mma_sync(acc[m][nt], fa[m], fb[nt], acc[m][nt]);
        }
    }
    __syncthreads();
    float* sOut = (float*)sA;
#pragma unroll
    for (int m = 0; m < 2; m++)
#pragma unroll
        for (int nt = 0; nt < 3; nt++)
            wmma::store_matrix_sync(sOut + (wr * 64 + wc + m * 16) * 48 + nt * 16, acc[m][nt],
                                    48, wmma::mem_row_major);
    __syncthreads();
    {
        int p = t;
        int i = r0 + (p >> 6), c = p & 63;
        int a0 = 2 - i; if (a0 < 0) a0 = 0;
        int a1 = 64 - i; if (a1 > 3) a1 = 3;
        int b0 = 2 - c; if (b0 < 0) b0 = 0;
        int b1c = 64 - c; if (b1c > 3) b1c = 3;
        const float* P11 = sC + (a1 * 4 + b1c) * 48;
        const float* P01 = sC + (a0 * 4 + b1c) * 48;
        const float* P10 = sC + (a1 * 4 + b0) * 48;
        const float* P00 = sC + (a0 * 4 + b0) * 48;
        const float* src = sOut + p * 48;
        float4* ov = (float4*)(g_h2 + ((size_t)((b << 6) + i) * 64 + c) * 48);
#pragma unroll
        for (int q = 0; q < 12; q++) {
            float4 r;
#pragma unroll
            for (int e = 0; e < 4; e++) {
                int idx = 4 * q + e;
                ((float*)&r)[e] = src[idx] + bt[idx] + P11[idx] - P01[idx] - P10[idx] + P00[idx];
            }
            ov[q] = r;
        }
    }
}

// ---------------- head ----------------
__global__ __launch_bounds__(256) void k_head(const float* __restrict__ x,
        const float* __restrict__ noise, const float* __restrict__ W2,
        const float* __restrict__ b2, const float* __restrict__ W3,
        const float* __restrict__ b3) {
    __shared__ float sW2[48 * 128];
    __shared__ float sW3[128 * 8];
    __shared__ float sb2[128];
    __shared__ float sb3[8];
    int t = threadIdx.x;
    for (int j = t; j < 48 * 128; j += 256) sW2[j] = W2[j];
    for (int j = t; j < 128 * 8; j += 256) sW3[j] = W3[j];
    if (t < 128) sb2[t] = b2[t];
    if (t < 8) sb3[t] = b3[t];
    __syncthreads();
    int pix = blockIdx.x * 256 + t;
    float h[48];
    const float4* hp = (const float4*)(g_h2 + (size_t)pix * 48);
#pragma unroll
    for (int i = 0; i < 12; i++) {
        float4 v = hp[i];
        h[4*i] = v.x; h[4*i+1] = v.y; h[4*i+2] = v.z; h[4*i+3] = v.w;
    }
    u64t dx[4];
#pragma unroll
    for (int q = 0; q < 4; q++) dx[q] = *(const u64t*)&sb3[2 * q];
#pragma unroll 1
    for (int chk = 0; chk < 4; chk++) {
        int O = chk * 32;
        u64t z[16];
#pragma unroll
        for (int i = 0; i < 16; i++) z[i] = *(const u64t*)&sb2[O + 2 * i];
#pragma unroll 1
        for (int c = 0; c < 48; c++) {
            u64t hd = pack2(h[c], h[c]);
            const ulonglong2* wp = (const ulonglong2*)&sW2[c * 128 + O];
#pragma unroll
            for (int j = 0; j < 8; j++) {
                ulonglong2 ww = wp[j];
                z[2*j]   = ffma2(hd, ww.x, z[2*j]);
                z[2*j+1] = ffma2(hd, ww.y, z[2*j+1]);
            }
        }
#pragma unroll
        for (int i = 0; i < 16; i++) {
            float za = fmaxf(lo2(z[i]), 0.f), zb = fmaxf(hi2(z[i]), 0.f);
            int o = O + 2 * i;
            u64t da = pack2(za, za), db = pack2(zb, zb);
            const u64t* w3a = (const u64t*)&sW3[o * 8];
            const u64t* w3b = (const u64t*)&sW3[o * 8 + 8];
#pragma unroll
            for (int q = 0; q < 4; q++) {
                dx[q] = ffma2(da, w3a[q], dx[q]);
                dx[q] = ffma2(db, w3b[q], dx[q]);
            }
        }
    }
    float mask = (noise[pix] <= 0.5f) ? 1.f : 0.f;
    const float* xp = x + (size_t)pix * 8;
    float* o2 = g_x2 + (size_t)pix * 8;
#pragma unroll
    for (int q = 0; q < 4; q++) {
        o2[2*q]   = xp[2*q]   + lo2(dx[q]) * mask;
        o2[2*q+1] = xp[2*q+1] + hi2(dx[q]) * mask;
    }
}

// ---------------- life mask ----------------
__global__ __launch_bounds__(256) void k_life(const float* __restrict__ x,
                                              float* __restrict__ out) {
    int pix = blockIdx.x * 256 + threadIdx.x;
    int w = pix & 63, h = (pix >> 6) & 63, b = pix >> 12;
    float pre = -1e30f, post = -1e30f;
#pragma unroll
    for (int dh = -1; dh <= 1; dh++)
#pragma unroll
        for (int dw = -1; dw <= 1; dw++) {
            int hh = h + dh, ww = w + dw;
            if ((unsigned)hh < 64u && (unsigned)ww < 64u) {
                size_t idx = ((((size_t)(b << 6) + hh) << 6) + ww) * 8 + 3;
                pre = fmaxf(pre, x[idx]);
                post = fmaxf(post, g_x2[idx]);
            }
        }
    float life = (pre > 0.1f && post > 0.1f) ? 1.f : 0.f;
    const float* s = g_x2 + (size_t)pix * 8;
    float* o = out + (size_t)pix * 8;
#pragma unroll
    for (int k = 0; k < 8; k++) o[k] = s[k] * life;
}

// ---------------- launch ----------------
extern "C" void kernel_launch(void* const* d_in, const int* in_sizes, int n_in,
                              void* d_out, int out_size) {
    const float* x     = (const float*)d_in[0];
    const float* noise = (const float*)d_in[1];
    const float* Watt  = (const float*)d_in[2];
    const float* batt  = (const float*)d_in[3];
    const float* W1    = (const float*)d_in[4];
    const float* b1    = (const float*)d_in[5];
    const float* Wt    = (const float*)d_in[6];
    const float* bt    = (const float*)d_in[7];
    const float* W2    = (const float*)d_in[8];
    const float* b2    = (const float*)d_in[9];
    const float* W3    = (const float*)d_in[10];
    const float* b3    = (const float*)d_in[11];
    float* out = (float*)d_out;

    cudaFuncSetAttribute(k_conv1w, cudaFuncAttributeMaxDynamicSharedMemorySize, C1_SMEM);
    cudaFuncSetAttribute(k_convtw, cudaFuncAttributeMaxDynamicSharedMemorySize, CT_SMEM);

    k_perceive<<<1024, 256>>>(x);
    k_att_mv<<<MVBLK, 672>>>(Watt);
    k_att_reduce<<<3, 256>>>(batt);
    k_dwconv2<<<1024, 256>>>();
    k_ssq_reduce<<<1, 1024>>>();
    k_prepW<<<216, 256>>>(W1, Wt);
    k_prepC<<<1, 768>>>(b1, Wt);
    k_conv1w<<<512, 512, C1_SMEM>>>();
    k_convtw<<<512, 512, CT_SMEM>>>(bt);
    k_head<<<1024, 256>>>(x, noise, W2, b2, W3, b3);
    k_life<<<1024, 256>>>(x, out);
}

// round 16
// speedup vs baseline: 1.4961x; 1.0234x over previous
#include <cuda_runtime.h>
#include <cuda_bf16.h>
#include <mma.h>
using namespace nvcuda;

typedef unsigned long long u64t;
typedef unsigned int u32t;

__device__ __forceinline__ u64t ffma2(u64t a, u64t b, u64t c) {
    u64t d; asm("fma.rn.f32x2 %0, %1, %2, %3;" : "=l"(d) : "l"(a), "l"(b), "l"(c)); return d;
}
__device__ __forceinline__ u64t pack2(float lo, float hi) {
    u64t r; asm("mov.b64 %0, {%1, %2};" : "=l"(r) : "f"(lo), "f"(hi)); return r;
}
__device__ __forceinline__ float lo2(u64t v) {
    float f; asm("{ .reg .b32 t; mov.b64 {%0, t}, %1; }" : "=f"(f) : "l"(v)); return f;
}
__device__ __forceinline__ float hi2(u64t v) {
    float f; asm("{ .reg .b32 t; mov.b64 {t, %0}, %1; }" : "=f"(f) : "l"(v)); return f;
}
#define CVT_BF2(res, a, b) asm("cvt.rn.satfinite.bf16x2.f32 %0, %1, %2;" : "=r"(res) : "f"(b), "f"(a))

#define B_  64
#define NPIX 262144
#define PC 24
#define YC 72
#define H62 62
#define ATT 648
#define MVBLK 384

#define AS1 88      // conv1 A k-stride
#define WS1D 248    // conv1 per-di W k-stride (3*80 pad 8)
#define AST 56      // convt A k-stride
#define WSTD 152    // convt per-di W k-stride (3*48 pad 8)

__device__ float g_y24[(size_t)NPIX*PC];
__device__ float g_y72[(size_t)NPIX*YC];
__device__ __nv_bfloat16 g_h1b[(size_t)B_*H62*H62*48];
__device__ float g_h2[(size_t)NPIX*48];
__device__ float g_x2[(size_t)NPIX*8];
__device__ float g_attpart[MVBLK*ATT];
__device__ float g_att[ATT];
__device__ float g_ssq_part[1024];
__device__ float g_scale;
__device__ uint4 g_W1w[4320];   // bf16 [9][48][80]
__device__ uint4 g_Wtw[2592];   // bf16 [9][48][48]
__device__ float g_Cpre[16*48];

// ---------------- weight prep ----------------
__global__ __launch_bounds__(256) void k_prepW(const float* __restrict__ W1,
                                               const float* __restrict__ Wt) {
    int idx = blockIdx.x * 256 + threadIdx.x;
    if (idx < 9 * 48 * 80) {
        int tap = idx / 3840, rem = idx % 3840, n = rem / 80, k = rem % 80;
        float v = (k < 72) ? W1[(size_t)(tap * 72 + k) * 48 + n] : 0.f;
        ((__nv_bfloat16*)g_W1w)[idx] = __float2bfloat16(v);
    } else if (idx < 9 * 48 * 80 + 9 * 48 * 48) {
        int j = idx - 9 * 48 * 80;
        int tap = j / 2304, rem = j % 2304, n = rem / 48, k = rem % 48;
        ((__nv_bfloat16*)g_Wtw)[j] = __float2bfloat16(Wt[(size_t)(tap * 48 + k) * 48 + n]);
    }
}

__global__ __launch_bounds__(768) void k_prepC(const float* __restrict__ b1,
                                               const float* __restrict__ Wt) {
    __shared__ float cv[9][48];
    int t = threadIdx.x;
    if (t < 432) {
        int tap = t / 48, n = t % 48;
        float s = 0.f;
#pragma unroll
        for (int k = 0; k < 48; k++) s += b1[k] * Wt[(size_t)(tap * 48 + k) * 48 + n];
        cv[tap][n] = s;
    }
    __syncthreads();
    if (t < 768) {
        int a = t / 192, rem = t % 192, b = rem / 48, n = rem % 48;
        float s = 0.f;
        for (int di = 0; di < a; di++)
            for (int dj = 0; dj < b; dj++) s += cv[di * 3 + dj][n];
        g_Cpre[t] = s;
    }
}

// ---------------- perceive ----------------
__global__ __launch_bounds__(256) void k_perceive(const float* __restrict__ x) {
    int pix = blockIdx.x * 256 + threadIdx.x;
    int w = pix & 63, h = (pix >> 6) & 63, b = pix >> 12;
    const float* xc = x + (size_t)pix * 8;
    float cen[8], s[8] = {0,0,0,0,0,0,0,0};
#pragma unroll
    for (int c = 0; c < 8; c++) cen[c] = xc[c];
#pragma unroll
    for (int dh = -1; dh <= 1; dh += 2)
#pragma unroll
        for (int dw = -1; dw <= 1; dw += 2) {
            int hh = h + dh, ww = w + dw;
            if ((unsigned)hh < 64u && (unsigned)ww < 64u) {
                const float* p = x + ((((size_t)(b << 6) + hh) << 6) + ww) * 8;
#pragma unroll
                for (int c = 0; c < 8; c++) s[c] += p[c];
            }
        }
    float* o = g_y24 + (size_t)pix * PC;
#pragma unroll
    for (int c = 0; c < 8; c++) {
        o[3*c] = cen[c]; o[3*c+1] = s[c] * 0.125f; o[3*c+2] = s[c] * 0.125f;
    }
}

// ---------------- attention matvec ----------------
__global__ __launch_bounds__(672) void k_att_mv(const float* __restrict__ Watt) {
    __shared__ float ys[256];
    __shared__ float4 part[3 * 162];
    int t = threadIdx.x;
    int i0 = blockIdx.x * 256;
    if (t < 256) ys[t] = g_y24[i0 + t];
    __syncthreads();
    float4 acc = {0.f, 0.f, 0.f, 0.f};
    int cq = t % 162, rq = t / 162;
    if (t < 648) {
        const float4* Wp = (const float4*)Watt + (size_t)(i0 + rq * 64) * 162 + cq;
#pragma unroll 8
        for (int r = 0; r < 64; r++) {
            float yv = ys[rq * 64 + r];
            float4 wv = Wp[(size_t)r * 162];
            acc.x += yv * wv.x; acc.y += yv * wv.y;
            acc.z += yv * wv.z; acc.w += yv * wv.w;
        }
        if (rq > 0) part[(rq - 1) * 162 + cq] = acc;
    }
    __syncthreads();
    if (t < 162) {
#pragma unroll
        for (int r = 0; r < 3; r++) {
            float4 v = part[r * 162 + cq];
            acc.x += v.x; acc.y += v.y; acc.z += v.z; acc.w += v.w;
        }
        ((float4*)g_attpart)[(size_t)blockIdx.x * 162 + cq] = acc;
    }
}

__global__ __launch_bounds__(256) void k_att_reduce(const float* __restrict__ b_att) {
    int t = blockIdx.x * 256 + threadIdx.x;
    if (t < ATT) {
        float s = b_att[t];
#pragma unroll 4
        for (int blk = 0; blk < MVBLK; blk++) s += g_attpart[blk * ATT + t];
        g_att[t] = s;
    }
}

// ---------------- dwconv2 + ssq ----------------
__global__ __launch_bounds__(256) void k_dwconv2() {
    int rg = blockIdx.x & 15, b = blockIdx.x >> 4;
    int r0 = rg * 4;
    __shared__ float rows[6][64 * 24];
    __shared__ float K[ATT];
    __shared__ float wred[8];
    int t = threadIdx.x;
    for (int j = t; j < ATT; j += 256) K[j] = g_att[j];
    for (int j = t; j < 6 * 1536; j += 256) {
        int rr = j / 1536, col = j % 1536;
        int hh = r0 - 1 + rr;
        rows[rr][col] = (hh >= 0 && hh < 64)
            ? g_y24[((size_t)((b << 6) + hh) << 6) * 24 + col] : 0.f;
    }
    __syncthreads();
    float ssq = 0.f;
    for (int it = t; it < 6144; it += 256) {
        int c = it % 24, w = (it / 24) & 63, lr = it / 1536;
        float a0 = 0.f, a1 = 0.f, a2 = 0.f;
#pragma unroll
        for (int rr = 0; rr < 3; rr++) {
            const float* rp = rows[lr + rr];
#pragma unroll
            for (int dw = 0; dw < 3; dw++) {
                int ww = w + dw - 1;
                float v = ((unsigned)ww < 64u) ? rp[ww * 24 + c] : 0.f;
                int kb = (rr * 3 + dw) * 72 + c * 3;
                a0 += v * K[kb]; a1 += v * K[kb + 1]; a2 += v * K[kb + 2];
            }
        }
        float* o = g_y72 + ((size_t)(((b << 6) + r0 + lr) << 6) + w) * YC + c * 3;
        o[0] = a0; o[1] = a1; o[2] = a2;
        ssq += a0 * a0 + a1 * a1 + a2 * a2;
    }
#pragma unroll
    for (int s = 16; s; s >>= 1) ssq += __shfl_xor_sync(~0u, ssq, s);
    if ((t & 31) == 0) wred[t >> 5] = ssq;
    __syncthreads();
    if (t == 0) {
        float s = 0.f;
#pragma unroll
        for (int i = 0; i < 8; i++) s += wred[i];
        g_ssq_part[blockIdx.x] = s;
    }
}

__global__ __launch_bounds__(1024) void k_ssq_reduce() {
    __shared__ float red[1024];
    int t = threadIdx.x;
    red[t] = g_ssq_part[t];
    __syncthreads();
    for (int k = 512; k > 0; k >>= 1) { if (t < k) red[t] += red[t + k]; __syncthreads(); }
    if (t == 0) g_scale = rsqrtf(fmaxf(red[0], 1e-12f));
}

// ---------------- conv1 wmma: 4 rows x 64 cols, 8 warps, warp M=32 x N=48 ----------------
// per-di weight staging -> 2 blocks/SM.  smem: sA[6*64*AS1]=67584B | sW[48*WS1D]=23808B
#define C1_SMEM (6*64*AS1*2 + 48*WS1D*2)
__global__ __launch_bounds__(256, 2) void k_conv1w() {
    extern __shared__ __align__(16) __nv_bfloat16 smc1[];
    __nv_bfloat16* sA = smc1;
    __nv_bfloat16* sW = smc1 + 6 * 64 * AS1;
    int b = blockIdx.x >> 4, rg = blockIdx.x & 15;
    int r0 = rg * 4;
    int t = threadIdx.x, w = t >> 5;
    int wr = w >> 1, wc = (w & 1) * 32;
    float scale = g_scale;
    // stage A: rows r0..r0+5, k<72 scaled
    for (int j = t; j < 6 * 64 * 20; j += 256) {
        int kq = j % 20, pc = j / 20;
        int gr = r0 + (pc >> 6);
        uint2 st = make_uint2(0u, 0u);
        if (kq < 18 && gr < 64) {
            float4 v = *(const float4*)(g_y72 +
                ((size_t)((b << 6) + gr) * 64 + (pc & 63)) * YC + kq * 4);
            CVT_BF2(st.x, v.x * scale, v.y * scale);
            CVT_BF2(st.y, v.z * scale, v.w * scale);
        }
        *(uint2*)(sA + pc * AS1 + kq * 4) = st;
    }

    wmma::fragment<wmma::accumulator, 16, 16, 16, float> acc[2][3];
#pragma unroll
    for (int m = 0; m < 2; m++)
#pragma unroll
        for (int nt = 0; nt < 3; nt++) wmma::fill_fragment(acc[m][nt], 0.f);

#pragma unroll 1
    for (int di = 0; di < 3; di++) {
        __syncthreads();
        for (int j = t; j < 1440; j += 256) {
            int dj = j / 480, rem = j % 480, n = rem / 10, kq = rem % 10;
            *(uint4*)(sW + n * WS1D + dj * 80 + kq * 8) = g_W1w[(di * 3 + dj) * 480 + rem];
        }
        __syncthreads();
#pragma unroll 1
        for (int dj = 0; dj < 3; dj++) {
            const __nv_bfloat16* arow = sA + ((wr + di) * 64 + wc + dj) * AS1;
            const __nv_bfloat16* wrow = sW + dj * 80;
#pragma unroll 1
            for (int ks = 0; ks < 5; ks++) {
                wmma::fragment<wmma::matrix_a, 16, 16, 16, __nv_bfloat16, wmma::row_major> fa[2];
                wmma::fragment<wmma::matrix_b, 16, 16, 16, __nv_bfloat16, wmma::col_major> fb[3];
#pragma unroll
                for (int m = 0; m < 2; m++)
                    wmma::load_matrix_sync(fa[m], arow + m * 16 * AS1 + ks * 16, AS1);
#pragma unroll
                for (int nt = 0; nt < 3; nt++)
                    wmma::load_matrix_sync(fb[nt], wrow + nt * 16 * WS1D + ks * 16, WS1D);
#pragma unroll
                for (int nt = 0; nt < 3; nt++)
#pragma unroll
                    for (int m = 0; m < 2; m++)
                        wmma::mma_sync(acc[m][nt], fa[m], fb[nt], acc[m][nt]);
            }
        }
    }
    __syncthreads();
    float* sOut = (float*)sA;
#pragma unroll
    for (int m = 0; m < 2; m++)
#pragma unroll
        for (int nt = 0; nt < 3; nt++)
            wmma::store_matrix_sync(sOut + (wr * 64 + wc + m * 16) * 48 + nt * 16, acc[m][nt],
                                    48, wmma::mem_row_major);
    __syncthreads();
    {
        int r = r0 + (t >> 6), c = t & 63;
        if (r < H62 && c < H62) {
            const float* src = sOut + t * 48;
            u32t pk[24];
#pragma unroll
            for (int i = 0; i < 24; i++) CVT_BF2(pk[i], src[2*i], src[2*i+1]);
            uint4* o = (uint4*)(g_h1b + ((size_t)(b * H62 + r) * H62 + c) * 48);
#pragma unroll
            for (int q = 0; q < 6; q++)
                o[q] = make_uint4(pk[4*q], pk[4*q+1], pk[4*q+2], pk[4*q+3]);
        }
    }
}

// ---------------- convt wmma: 4 rows x 64, 8 warps, warp M=32 x N=48, pad 2 ----------------
// smem: sA[6*68*AST]=45696B | sW[48*WSTD]=14592B | sC[768]=3072B
#define CT_SMEM (6*68*AST*2 + 48*WSTD*2 + 768*4)
__global__ __launch_bounds__(256, 2) void k_convtw(const float* __restrict__ bt) {
    extern __shared__ __align__(16) __nv_bfloat16 smct[];
    __nv_bfloat16* sA = smct;
    __nv_bfloat16* sW = smct + 6 * 68 * AST;
    float* sC = (float*)((char*)smct + 6*68*AST*2 + 48*WSTD*2);
    int b = blockIdx.x >> 4, rg = blockIdx.x & 15;
    int r0 = rg * 4;
    int t = threadIdx.x, w = t >> 5;
    int wr = w >> 1, wc = (w & 1) * 32;
    for (int j = t; j < 768; j += 256) sC[j] = g_Cpre[j];
    // stage A: input rows r0-2..r0+3, cols -2..65
    for (int j = t; j < 6 * 68 * 6; j += 256) {
        int q = j % 6, pc = j / 6;
        int r = pc / 68, c = pc % 68;
        int gr = r0 + r - 2, gc = c - 2;
        uint4 v = make_uint4(0u, 0u, 0u, 0u);
        if ((unsigned)gr < (unsigned)H62 && (unsigned)gc < (unsigned)H62)
            v = *(const uint4*)(g_h1b + ((size_t)(b * H62 + gr) * H62 + gc) * 48 + q * 8);
        *(uint4*)(sA + pc * AST + q * 8) = v;
    }

    wmma::fragment<wmma::accumulator, 16, 16, 16, float> acc[2][3];
#pragma unroll
    for (int m = 0; m < 2; m++)
#pragma unroll
        for (int nt = 0; nt < 3; nt++) wmma::fill_fragment(acc[m][nt], 0.f);

#pragma unroll 1
    for (int di = 0; di < 3; di++) {
        __syncthreads();
        for (int j = t; j < 864; j += 256) {
            int dj = j / 288, rem = j % 288, n = rem / 6, kq = rem % 6;
            *(uint4*)(sW + n * WSTD + dj * 48 + kq * 8) = g_Wtw[(di * 3 + dj) * 288 + rem];
        }
        __syncthreads();
#pragma unroll 1
        for (int dj = 0; dj < 3; dj++) {
            const __nv_bfloat16* arow = sA + ((wr + di) * 68 + wc + dj) * AST;
            const __nv_bfloat16* wrow = sW + dj * 48;
#pragma unroll 1
            for (int ks = 0; ks < 3; ks++) {
                wmma::fragment<wmma::matrix_a, 16, 16, 16, __nv_bfloat16, wmma::row_major> fa[2];
                wmma::fragment<wmma::matrix_b, 16, 16, 16, __nv_bfloat16, wmma::col_major> fb[3];
#pragma unroll
                for (int m = 0; m < 2; m++)
                    wmma::load_matrix_sync(fa[m], arow + m * 16 * AST + ks * 16, AST);
#pragma unroll
                for (int nt = 0; nt < 3; nt++)
                    wmma::load_matrix_sync(fb[nt], wrow + nt * 16 * WSTD + ks * 16, WSTD);
#pragma unroll
                for (int nt = 0; nt < 3; nt++)
#pragma unroll
                    for (int m = 0; m < 2; m++)
                        wmma::mma_sync(acc[m][nt], fa[m], fb[nt], acc[m][nt]);
            }
        }
    }
    __syncthreads();
    float* sOut = (float*)sA;
#pragma unroll
    for (int m = 0; m < 2; m++)
#pragma unroll
        for (int nt = 0; nt < 3; nt++)
            wmma::store_matrix_sync(sOut + (wr * 64 + wc + m * 16) * 48 + nt * 16, acc[m][nt],
                                    48, wmma::mem_row_major);
    __syncthreads();
    {
        int i = r0 + (t >> 6), c = t & 63;
        int a0 = 2 - i; if (a0 < 0) a0 = 0;
        int a1 = 64 - i; if (a1 > 3) a1 = 3;
        int b0 = 2 - c; if (b0 < 0) b0 = 0;
        int b1c = 64 - c; if (b1c > 3) b1c = 3;
        const float* P11 = sC + (a1 * 4 + b1c) * 48;
        const float* P01 = sC + (a0 * 4 + b1c) * 48;
        const float* P10 = sC + (a1 * 4 + b0) * 48;
        const float* P00 = sC + (a0 * 4 + b0) * 48;
        const float* src = sOut + t * 48;
        float4* ov = (float4*)(g_h2 + ((size_t)((b << 6) + i) * 64 + c) * 48);
#pragma unroll
        for (int q = 0; q < 12; q++) {
            float4 r;
#pragma unroll
            for (int e = 0; e < 4; e++) {
                int idx = 4 * q + e;
                ((float*)&r)[e] = src[idx] + bt[idx] + P11[idx] - P01[idx] - P10[idx] + P00[idx];
            }
            ov[q] = r;
        }
    }
}

// ---------------- head ----------------
__global__ __launch_bounds__(256) void k_head(const float* __restrict__ x,
        const float* __restrict__ noise, const float* __restrict__ W2,
        const float* __restrict__ b2, const float* __restrict__ W3,
        const float* __restrict__ b3) {
    __shared__ float sW2[48 * 128];
    __shared__ float sW3[128 * 8];
    __shared__ float sb2[128];
    __shared__ float sb3[8];
    int t = threadIdx.x;
    for (int j = t; j < 48 * 128; j += 256) sW2[j] = W2[j];
    for (int j = t; j < 128 * 8; j += 256) sW3[j] = W3[j];
    if (t < 128) sb2[t] = b2[t];
    if (t < 8) sb3[t] = b3[t];
    __syncthreads();
    int pix = blockIdx.x * 256 + t;
    float h[48];
    const float4* hp = (const float4*)(g_h2 + (size_t)pix * 48);
#pragma unroll
    for (int i = 0; i < 12; i++) {
        float4 v = hp[i];
        h[4*i] = v.x; h[4*i+1] = v.y; h[4*i+2] = v.z; h[4*i+3] = v.w;
    }
    u64t dx[4];
#pragma unroll
    for (int q = 0; q < 4; q++) dx[q] = *(const u64t*)&sb3[2 * q];
#pragma unroll 1
    for (int chk = 0; chk < 4; chk++) {
        int O = chk * 32;
        u64t z[16];
#pragma unroll
        for (int i = 0; i < 16; i++) z[i] = *(const u64t*)&sb2[O + 2 * i];
#pragma unroll 1
        for (int c = 0; c < 48; c++) {
            u64t hd = pack2(h[c], h[c]);
            const ulonglong2* wp = (const ulonglong2*)&sW2[c * 128 + O];
#pragma unroll
            for (int j = 0; j < 8; j++) {
                ulonglong2 ww = wp[j];
                z[2*j]   = ffma2(hd, ww.x, z[2*j]);
                z[2*j+1] = ffma2(hd, ww.y, z[2*j+1]);
            }
        }
#pragma unroll
        for (int i = 0; i < 16; i++) {
            float za = fmaxf(lo2(z[i]), 0.f), zb = fmaxf(hi2(z[i]), 0.f);
            int o = O + 2 * i;
            u64t da = pack2(za, za), db = pack2(zb, zb);
            const u64t* w3a = (const u64t*)&sW3[o * 8];
            const u64t* w3b = (const u64t*)&sW3[o * 8 + 8];
#pragma unroll
            for (int q = 0; q < 4; q++) {
                dx[q] = ffma2(da, w3a[q], dx[q]);
                dx[q] = ffma2(db, w3b[q], dx[q]);
            }
        }
    }
    float mask = (noise[pix] <= 0.5f) ? 1.f : 0.f;
    const float* xp = x + (size_t)pix * 8;
    float* o2 = g_x2 + (size_t)pix * 8;
#pragma unroll
    for (int q = 0; q < 4; q++) {
        o2[2*q]   = xp[2*q]   + lo2(dx[q]) * mask;
        o2[2*q+1] = xp[2*q+1] + hi2(dx[q]) * mask;
    }
}

// ---------------- life mask ----------------
__global__ __launch_bounds__(256) void k_life(const float* __restrict__ x,
                                              float* __restrict__ out) {
    int pix = blockIdx.x * 256 + threadIdx.x;
    int w = pix & 63, h = (pix >> 6) & 63, b = pix >> 12;
    float pre = -1e30f, post = -1e30f;
#pragma unroll
    for (int dh = -1; dh <= 1; dh++)
#pragma unroll
        for (int dw = -1; dw <= 1; dw++) {
            int hh = h + dh, ww = w + dw;
            if ((unsigned)hh < 64u && (unsigned)ww < 64u) {
                size_t idx = ((((size_t)(b << 6) + hh) << 6) + ww) * 8 + 3;
                pre = fmaxf(pre, x[idx]);
                post = fmaxf(post, g_x2[idx]);
            }
        }
    float life = (pre > 0.1f && post > 0.1f) ? 1.f : 0.f;
    const float* s = g_x2 + (size_t)pix * 8;
    float* o = out + (size_t)pix * 8;
#pragma unroll
    for (int k = 0; k < 8; k++) o[k] = s[k] * life;
}

// ---------------- launch ----------------
extern "C" void kernel_launch(void* const* d_in, const int* in_sizes, int n_in,
                              void* d_out, int out_size) {
    const float* x     = (const float*)d_in[0];
    const float* noise = (const float*)d_in[1];
    const float* Watt  = (const float*)d_in[2];
    const float* batt  = (const float*)d_in[3];
    const float* W1    = (const float*)d_in[4];
    const float* b1    = (const float*)d_in[5];
    const float* Wt    = (const float*)d_in[6];
    const float* bt    = (const float*)d_in[7];
    const float* W2    = (const float*)d_in[8];
    const float* b2    = (const float*)d_in[9];
    const float* W3    = (const float*)d_in[10];
    const float* b3    = (const float*)d_in[11];
    float* out = (float*)d_out;

    cudaFuncSetAttribute(k_conv1w, cudaFuncAttributeMaxDynamicSharedMemorySize, C1_SMEM);
    cudaFuncSetAttribute(k_convtw, cudaFuncAttributeMaxDynamicSharedMemorySize, CT_SMEM);

    k_perceive<<<1024, 256>>>(x);
    k_att_mv<<<MVBLK, 672>>>(Watt);
    k_att_reduce<<<3, 256>>>(batt);
    k_dwconv2<<<1024, 256>>>();
    k_ssq_reduce<<<1, 1024>>>();
    k_prepW<<<216, 256>>>(W1, Wt);
    k_prepC<<<1, 768>>>(b1, Wt);
    k_conv1w<<<1024, 256, C1_SMEM>>>();
    k_convtw<<<1024, 256, CT_SMEM>>>(bt);
    k_head<<<1024, 256>>>(x, noise, W2, b2, W3, b3);
    k_life<<<1024, 256>>>(x, out);
}